// round 4
// baseline (speedup 1.0000x reference)
#include <cuda_runtime.h>

#define N_CAP 20480
#define DEG_CAP 64      // fixed-stride edge-table width; deg ~ Poisson(16)
#define CH 16           // edges per accumulation chunk (8 subtask threads/edge)

// ---------------- device scratch ----------------
// d_count is zero at module load; ps_kernel re-zeros its node at the end of
// every call, so each graph replay starts from a clean cursor.
__device__ int d_count[N_CAP];
__device__ int d_elist[N_CAP * DEG_CAP];

// ---------------- phase 1: scatter edge ids into fixed-stride table --------
__global__ void scatter_kernel(const int* __restrict__ ei, int E) {
    int e = blockIdx.x * blockDim.x + threadIdx.x;
    if (e < E) {
        int node = ei[e];
        int p = atomicAdd(&d_count[node], 1);
        if (p < DEG_CAP) d_elist[node * DEG_CAP + p] = e;
    }
}

// ---------------- phase 2: per-node features + power spectrum --------------
__global__ __launch_bounds__(128, 12) void ps_kernel(
    const float* __restrict__ pos, const float* __restrict__ cells,
    const int* __restrict__ species, const int* __restrict__ ei,
    const int* __restrict__ shifts, const float* __restrict__ embed,
    const float* __restrict__ mu, const float* __restrict__ sigma,
    float* __restrict__ out, int N, int E)
{
    __shared__ float Ysh[16][CH + 1];   // [m][edge]
    __shared__ float wsh[CH][40];       // [edge][q], pad 40
    __shared__ float csh[16][32];
    __shared__ int   elist[DEG_CAP];
    __shared__ int   esort[DEG_CAP];
    __shared__ float s_embed[16];
    __shared__ float s_mu[8];
    __shared__ float s_cell[9];
    __shared__ float s_pi[3];

    int node = blockIdx.x;
    int t = threadIdx.x;

    if (t < 16) s_embed[t] = embed[t];
    if (t < 8)  s_mu[t] = mu[t];
    if (t < 9)  s_cell[t] = cells[t];
    if (t < 3)  s_pi[t] = pos[3 * node + t];

    int deg = d_count[node];
    if (deg > DEG_CAP) deg = DEG_CAP;

    for (int k = t; k < deg; k += 128) elist[k] = d_elist[node * DEG_CAP + k];
    __syncthreads();
    // deterministic accumulation order: rank-sort unique edge ids
    for (int k = t; k < deg; k += 128) {
        int e = elist[k], rank = 0;
        for (int x = 0; x < deg; x++) rank += (elist[x] < e);
        esort[rank] = e;
    }
    __syncthreads();

    float sg = sigma[0];
    float inv2s2 = 1.0f / (2.0f * sg * sg);

    int w = t >> 5;   // warp id
    int q = t & 31;   // lane
    float cacc0 = 0.0f, cacc1 = 0.0f, cacc2 = 0.0f, cacc3 = 0.0f;

    int eidx = t >> 3;   // 0..15: edge within chunk
    int sub  = t & 7;    // 0..7: subtask

    for (int base = 0; base < deg; base += CH) {
        int ne = deg - base; if (ne > CH) ne = CH;
        if (eidx < ne) {
            int e = esort[base + eidx];
            int j = ei[E + e];
            float rx = pos[3 * j + 0] - s_pi[0];
            float ry = pos[3 * j + 1] - s_pi[1];
            float rz = pos[3 * j + 2] - s_pi[2];
            float sx = (float)shifts[3 * e + 0];
            float sy = (float)shifts[3 * e + 1];
            float sz = (float)shifts[3 * e + 2];
            rx += sx * s_cell[0] + sy * s_cell[3] + sz * s_cell[6];
            ry += sx * s_cell[1] + sy * s_cell[4] + sz * s_cell[7];
            rz += sx * s_cell[2] + sy * s_cell[5] + sz * s_cell[8];

            float r2 = rx * rx + ry * ry + rz * rz + 1e-12f;
            float rinv = rsqrtf(r2);
            float r = r2 * rinv;
            float x = rx * rinv, y = ry * rinv, z = rz * rinv;

            float fcut = (r < 5.0f) ? 0.5f * (cospif(r * 0.2f) + 1.0f) : 0.0f;

            int sp = species[j];
            {   // radial: this thread owns n = sub
                float d = r - s_mu[sub];
                float Rn = __expf(-d * d * inv2s2) * fcut;
                wsh[eidx][0 * 8 + sub] = s_embed[4 * sp + 0] * Rn;
                wsh[eidx][1 * 8 + sub] = s_embed[4 * sp + 1] * Rn;
                wsh[eidx][2 * 8 + sub] = s_embed[4 * sp + 2] * Rn;
                wsh[eidx][3 * 8 + sub] = s_embed[4 * sp + 3] * Rn;
            }
            // spherical harmonics: this thread owns m = 2*sub, 2*sub+1
            float x2 = x * x, y2 = y * y, z2 = z * z;
            float ya, yb;
            switch (sub) {
                case 0: ya = 0.28209479177387814f;
                        yb = 0.4886025119029199f * y; break;
                case 1: ya = 0.4886025119029199f * z;
                        yb = 0.4886025119029199f * x; break;
                case 2: ya = 1.0925484305920792f * x * y;
                        yb = 1.0925484305920792f * y * z; break;
                case 3: ya = 0.31539156525252005f * (3.0f * z2 - 1.0f);
                        yb = 1.0925484305920792f * x * z; break;
                case 4: ya = 0.5462742152960396f * (x2 - y2);
                        yb = 0.5900435899266435f * y * (3.0f * x2 - y2); break;
                case 5: ya = 2.890611442640554f * x * y * z;
                        yb = 0.4570457994644658f * y * (5.0f * z2 - 1.0f); break;
                case 6: ya = 0.3731763325901154f * z * (5.0f * z2 - 3.0f);
                        yb = 0.4570457994644658f * x * (5.0f * z2 - 1.0f); break;
                default: ya = 1.445305721320277f * z * (x2 - y2);
                         yb = 0.5900435899266435f * x * (x2 - 3.0f * y2); break;
            }
            Ysh[2 * sub + 0][eidx] = ya;
            Ysh[2 * sub + 1][eidx] = yb;
        }
        __syncthreads();
#pragma unroll 4
        for (int e2i = 0; e2i < ne; e2i++) {
            float wv = wsh[e2i][q];
            cacc0 = fmaf(Ysh[w +  0][e2i], wv, cacc0);
            cacc1 = fmaf(Ysh[w +  4][e2i], wv, cacc1);
            cacc2 = fmaf(Ysh[w +  8][e2i], wv, cacc2);
            cacc3 = fmaf(Ysh[w + 12][e2i], wv, cacc3);
        }
        __syncthreads();
    }

    csh[w +  0][q] = cacc0;
    csh[w +  4][q] = cacc1;
    csh[w +  8][q] = cacc2;
    csh[w + 12][q] = cacc3;
    __syncthreads();

    // epilogue: warp l computes its 32x32 l-block entirely from registers +
    // shuffles. cm[k] = c[l*l + k][lane]; out[qq][lane] = cg * sum_k
    // shfl(cm[k], qq) * cm[k]. Zero LDS in the hot loop.
    {
        int l = w;
        int m0 = l * l;
        int cnt = 2 * l + 1;           // 1,3,5,7
        const float cgv[4] = {1.0f, 0.5773502691896258f,
                              0.4472135954999579f, 0.3779644730092272f};
        float cg = cgv[l];
        float cm[7];
#pragma unroll 7
        for (int k = 0; k < 7; k++)
            cm[k] = (k < cnt) ? csh[m0 + k][q] : 0.0f;

        float* ob = out + (size_t)node * 4096 + (size_t)l * 1024 + q;
#pragma unroll 8
        for (int qq = 0; qq < 32; qq++) {
            float s = 0.0f;
#pragma unroll 7
            for (int k = 0; k < 7; k++) {
                if (k < cnt) {
                    float a = __shfl_sync(0xffffffffu, cm[k], qq);
                    s = fmaf(a, cm[k], s);
                }
            }
            __stcs(ob + qq * 32, cg * s);
        }
    }

    // reset cursor for the next graph replay
    if (t == 0) d_count[node] = 0;
}

extern "C" void kernel_launch(void* const* d_in, const int* in_sizes, int n_in,
                              void* d_out, int out_size) {
    const float* pos     = (const float*)d_in[0];
    const float* cells   = (const float*)d_in[1];
    const int*   species = (const int*)  d_in[2];
    const int*   ei      = (const int*)  d_in[3];
    const int*   shifts  = (const int*)  d_in[4];
    const float* embed   = (const float*)d_in[5];
    const float* mu      = (const float*)d_in[6];
    const float* sigma   = (const float*)d_in[7];
    int N = in_sizes[0] / 3;
    int E = in_sizes[3] / 2;
    float* out = (float*)d_out;

    scatter_kernel<<<(E + 511) / 512, 512>>>(ei, E);
    ps_kernel<<<N, 128>>>(pos, cells, species, ei, shifts, embed, mu, sigma, out, N, E);
}

// round 5
// speedup vs baseline: 1.7045x; 1.7045x over previous
#include <cuda_runtime.h>

#define N_CAP 20480
#define DEG_CAP 64      // fixed-stride edge-table width; deg ~ Poisson(16)
#define CH 16           // edges per accumulation chunk (8 subtask threads/edge)

// ---------------- device scratch ----------------
// d_count is zero at module load; ps_kernel re-zeros its node at the end of
// every call, so each graph replay starts from a clean cursor.
__device__ int d_count[N_CAP];
__device__ int d_elist[N_CAP * DEG_CAP];

// ---------------- phase 1: scatter edge ids into fixed-stride table --------
__global__ void scatter_kernel(const int* __restrict__ ei, int E) {
    int e = blockIdx.x * blockDim.x + threadIdx.x;
    if (e < E) {
        int node = ei[e];
        int p = atomicAdd(&d_count[node], 1);
        if (p < DEG_CAP) d_elist[node * DEG_CAP + p] = e;
    }
}

// ---------------- phase 2: per-node features + power spectrum --------------
__global__ __launch_bounds__(128, 12) void ps_kernel(
    const float* __restrict__ pos, const float* __restrict__ cells,
    const int* __restrict__ species, const int* __restrict__ ei,
    const int* __restrict__ shifts, const float* __restrict__ embed,
    const float* __restrict__ mu, const float* __restrict__ sigma,
    float* __restrict__ out, int N, int E)
{
    __shared__ __align__(16) float Ysh[CH][16];  // [edge][m]: 64B rows
    __shared__ float wsh[CH][40];                // [edge][q], pad 40
    __shared__ __align__(16) float csh[16][32];  // [m][q]
    __shared__ int   elist[DEG_CAP];
    __shared__ int   esort[DEG_CAP];
    __shared__ float s_embed[16];
    __shared__ float s_mu[8];
    __shared__ float s_cell[9];
    __shared__ float s_pi[3];

    int node = blockIdx.x;
    int t = threadIdx.x;

    if (t < 16) s_embed[t] = embed[t];
    if (t < 8)  s_mu[t] = mu[t];
    if (t < 9)  s_cell[t] = cells[t];
    if (t < 3)  s_pi[t] = pos[3 * node + t];

    int deg = d_count[node];
    if (deg > DEG_CAP) deg = DEG_CAP;

    for (int k = t; k < deg; k += 128) elist[k] = d_elist[node * DEG_CAP + k];
    __syncthreads();
    // deterministic accumulation order: rank-sort unique edge ids
    for (int k = t; k < deg; k += 128) {
        int e = elist[k], rank = 0;
        for (int x = 0; x < deg; x++) rank += (elist[x] < e);
        esort[rank] = e;
    }
    __syncthreads();

    float sg = sigma[0];
    float inv2s2 = 1.0f / (2.0f * sg * sg);

    int w = t >> 5;   // warp id: owns m = 4w..4w+3
    int q = t & 31;   // lane
    float cacc0 = 0.0f, cacc1 = 0.0f, cacc2 = 0.0f, cacc3 = 0.0f;

    int eidx = t >> 3;   // 0..15: edge within chunk
    int sub  = t & 7;    // 0..7: subtask

    for (int base = 0; base < deg; base += CH) {
        int ne = deg - base; if (ne > CH) ne = CH;
        if (eidx < ne) {
            int e = esort[base + eidx];
            int j = ei[E + e];
            float rx = pos[3 * j + 0] - s_pi[0];
            float ry = pos[3 * j + 1] - s_pi[1];
            float rz = pos[3 * j + 2] - s_pi[2];
            float sx = (float)shifts[3 * e + 0];
            float sy = (float)shifts[3 * e + 1];
            float sz = (float)shifts[3 * e + 2];
            rx += sx * s_cell[0] + sy * s_cell[3] + sz * s_cell[6];
            ry += sx * s_cell[1] + sy * s_cell[4] + sz * s_cell[7];
            rz += sx * s_cell[2] + sy * s_cell[5] + sz * s_cell[8];

            float r2 = rx * rx + ry * ry + rz * rz + 1e-12f;
            float rinv = rsqrtf(r2);
            float r = r2 * rinv;
            float x = rx * rinv, y = ry * rinv, z = rz * rinv;

            float fcut = (r < 5.0f) ? 0.5f * (cospif(r * 0.2f) + 1.0f) : 0.0f;

            int sp = species[j];
            {   // radial: this thread owns n = sub
                float d = r - s_mu[sub];
                float Rn = __expf(-d * d * inv2s2) * fcut;
                wsh[eidx][0 * 8 + sub] = s_embed[4 * sp + 0] * Rn;
                wsh[eidx][1 * 8 + sub] = s_embed[4 * sp + 1] * Rn;
                wsh[eidx][2 * 8 + sub] = s_embed[4 * sp + 2] * Rn;
                wsh[eidx][3 * 8 + sub] = s_embed[4 * sp + 3] * Rn;
            }
            // spherical harmonics: this thread owns m = 2*sub, 2*sub+1
            float x2 = x * x, y2 = y * y, z2 = z * z;
            float ya, yb;
            switch (sub) {
                case 0: ya = 0.28209479177387814f;
                        yb = 0.4886025119029199f * y; break;
                case 1: ya = 0.4886025119029199f * z;
                        yb = 0.4886025119029199f * x; break;
                case 2: ya = 1.0925484305920792f * x * y;
                        yb = 1.0925484305920792f * y * z; break;
                case 3: ya = 0.31539156525252005f * (3.0f * z2 - 1.0f);
                        yb = 1.0925484305920792f * x * z; break;
                case 4: ya = 0.5462742152960396f * (x2 - y2);
                        yb = 0.5900435899266435f * y * (3.0f * x2 - y2); break;
                case 5: ya = 2.890611442640554f * x * y * z;
                        yb = 0.4570457994644658f * y * (5.0f * z2 - 1.0f); break;
                case 6: ya = 0.3731763325901154f * z * (5.0f * z2 - 3.0f);
                        yb = 0.4570457994644658f * x * (5.0f * z2 - 1.0f); break;
                default: ya = 1.445305721320277f * z * (x2 - y2);
                         yb = 0.5900435899266435f * x * (x2 - 3.0f * y2); break;
            }
            // STS.64: m = 2sub, 2sub+1 contiguous, 8B aligned
            float2* yrow = (float2*)&Ysh[eidx][2 * sub];
            *yrow = make_float2(ya, yb);
        }
        __syncthreads();
        const float4* Y4 = (const float4*)Ysh;   // [edge][4] float4s
        if (ne == CH) {
#pragma unroll
            for (int e2i = 0; e2i < CH; e2i++) {
                float wv = wsh[e2i][q];
                float4 yv = Y4[e2i * 4 + w];     // broadcast LDS.128
                cacc0 = fmaf(yv.x, wv, cacc0);
                cacc1 = fmaf(yv.y, wv, cacc1);
                cacc2 = fmaf(yv.z, wv, cacc2);
                cacc3 = fmaf(yv.w, wv, cacc3);
            }
        } else {
            for (int e2i = 0; e2i < ne; e2i++) {
                float wv = wsh[e2i][q];
                float4 yv = Y4[e2i * 4 + w];
                cacc0 = fmaf(yv.x, wv, cacc0);
                cacc1 = fmaf(yv.y, wv, cacc1);
                cacc2 = fmaf(yv.z, wv, cacc2);
                cacc3 = fmaf(yv.w, wv, cacc3);
            }
        }
        __syncthreads();
    }

    csh[4 * w + 0][q] = cacc0;
    csh[4 * w + 1][q] = cacc1;
    csh[4 * w + 2][q] = cacc2;
    csh[4 * w + 3][q] = cacc3;
    __syncthreads();

    // epilogue: thread owns float4 column rb = t&7 and q-rows {qh, qh+16},
    // qh = t>>3. Per l-block: load (2l+1) float4 v-vectors once, use for both
    // q-rows. All LDS broadcast/conflict-free; stores coalesced STG.128.
    {
        int rb = t & 7;
        int qh = t >> 3;           // 0..15
        const float4* csh4 = (const float4*)csh;   // [m][8]
        float4* out4 = (float4*)(out + (size_t)node * 4096);
        const float cgv[4] = {1.0f, 0.5773502691896258f,
                              0.4472135954999579f, 0.3779644730092272f};
        int m0 = 0;
#pragma unroll
        for (int l = 0; l < 4; l++) {
            int cnt = 2 * l + 1;
            float4 acc0 = make_float4(0.f, 0.f, 0.f, 0.f);
            float4 acc1 = make_float4(0.f, 0.f, 0.f, 0.f);
#pragma unroll 7
            for (int k = 0; k < 7; k++) {
                if (k < cnt) {
                    float4 v = csh4[(m0 + k) * 8 + rb];
                    float a0 = csh[m0 + k][qh];
                    float a1 = csh[m0 + k][qh + 16];
                    acc0.x = fmaf(a0, v.x, acc0.x);
                    acc0.y = fmaf(a0, v.y, acc0.y);
                    acc0.z = fmaf(a0, v.z, acc0.z);
                    acc0.w = fmaf(a0, v.w, acc0.w);
                    acc1.x = fmaf(a1, v.x, acc1.x);
                    acc1.y = fmaf(a1, v.y, acc1.y);
                    acc1.z = fmaf(a1, v.z, acc1.z);
                    acc1.w = fmaf(a1, v.w, acc1.w);
                }
            }
            float cg = cgv[l];
            acc0.x *= cg; acc0.y *= cg; acc0.z *= cg; acc0.w *= cg;
            acc1.x *= cg; acc1.y *= cg; acc1.z *= cg; acc1.w *= cg;
            __stcs(&out4[l * 256 + qh * 8 + rb], acc0);
            __stcs(&out4[l * 256 + (qh + 16) * 8 + rb], acc1);
            m0 += cnt;
        }
    }

    // reset cursor for the next graph replay
    if (t == 0) d_count[node] = 0;
}

extern "C" void kernel_launch(void* const* d_in, const int* in_sizes, int n_in,
                              void* d_out, int out_size) {
    const float* pos     = (const float*)d_in[0];
    const float* cells   = (const float*)d_in[1];
    const int*   species = (const int*)  d_in[2];
    const int*   ei      = (const int*)  d_in[3];
    const int*   shifts  = (const int*)  d_in[4];
    const float* embed   = (const float*)d_in[5];
    const float* mu      = (const float*)d_in[6];
    const float* sigma   = (const float*)d_in[7];
    int N = in_sizes[0] / 3;
    int E = in_sizes[3] / 2;
    float* out = (float*)d_out;

    scatter_kernel<<<(E + 511) / 512, 512>>>(ei, E);
    ps_kernel<<<N, 128>>>(pos, cells, species, ei, shifts, embed, mu, sigma, out, N, E);
}

// round 8
// speedup vs baseline: 1.7239x; 1.0114x over previous
#include <cuda_runtime.h>

#define N_CAP 20480
#define DEG_CAP 64      // fixed-stride edge-table width; deg ~ Poisson(16)
#define CH 16           // edges per accumulation chunk (8 subtask threads/edge)

// ---------------- device scratch ----------------
// d_count is zero at module load; ps_kernel re-zeros its node at the end of
// every call, so each graph replay starts from a clean cursor.
__device__ int d_count[N_CAP];
__device__ int d_elist[N_CAP * DEG_CAP];

// ---------------- phase 1: scatter edge ids (4 indep chains/thread) --------
__global__ void scatter_kernel(const int4* __restrict__ ei4, int E4) {
    int i = blockIdx.x * blockDim.x + threadIdx.x;
    if (i < E4) {
        int4 v = ei4[i];
        int e = 4 * i;
        int p0 = atomicAdd(&d_count[v.x], 1);
        int p1 = atomicAdd(&d_count[v.y], 1);
        int p2 = atomicAdd(&d_count[v.z], 1);
        int p3 = atomicAdd(&d_count[v.w], 1);
        if (p0 < DEG_CAP) d_elist[v.x * DEG_CAP + p0] = e + 0;
        if (p1 < DEG_CAP) d_elist[v.y * DEG_CAP + p1] = e + 1;
        if (p2 < DEG_CAP) d_elist[v.z * DEG_CAP + p2] = e + 2;
        if (p3 < DEG_CAP) d_elist[v.w * DEG_CAP + p3] = e + 3;
    }
}

// ---------------- phase 2: per-node features + power spectrum --------------
__global__ __launch_bounds__(128, 12) void ps_kernel(
    const float* __restrict__ pos, const float* __restrict__ cells,
    const int* __restrict__ species, const int* __restrict__ ei,
    const int* __restrict__ shifts, const float* __restrict__ embed,
    const float* __restrict__ mu, const float* __restrict__ sigma,
    float* __restrict__ out, int N, int E)
{
    __shared__ __align__(16) float Ysh[CH][16];  // [edge][m]: 64B rows
    __shared__ float wsh[CH][40];                // [edge][q], pad 40
    __shared__ __align__(16) float csh[16][32];  // [m][q]
    __shared__ int   elist[DEG_CAP];
    __shared__ int   esort[DEG_CAP];
    __shared__ float s_embed[16];
    __shared__ float s_mu[8];
    __shared__ float s_cell[9];
    __shared__ float s_pi[3];

    int node = blockIdx.x;
    int t = threadIdx.x;

    if (t < 16) s_embed[t] = embed[t];
    if (t < 8)  s_mu[t] = mu[t];
    if (t < 9)  s_cell[t] = cells[t];
    if (t < 3)  s_pi[t] = pos[3 * node + t];

    int deg = d_count[node];
    if (deg > DEG_CAP) deg = DEG_CAP;

    for (int k = t; k < deg; k += 128) elist[k] = d_elist[node * DEG_CAP + k];
    __syncthreads();
    // deterministic accumulation order: rank-sort unique edge ids
    for (int k = t; k < deg; k += 128) {
        int e = elist[k], rank = 0;
        for (int x = 0; x < deg; x++) rank += (elist[x] < e);
        esort[rank] = e;
    }
    __syncthreads();

    float sg = sigma[0];
    float inv2s2 = 1.0f / (2.0f * sg * sg);

    int w = t >> 5;   // warp id: owns m = 4w..4w+3
    int q = t & 31;   // lane
    float cacc0 = 0.0f, cacc1 = 0.0f, cacc2 = 0.0f, cacc3 = 0.0f;

    int eidx = t >> 3;   // 0..15: edge within chunk
    int sub  = t & 7;    // 0..7: subtask

    for (int base = 0; base < deg; base += CH) {
        int ne = deg - base; if (ne > CH) ne = CH;
        if (eidx < ne) {
            int e = esort[base + eidx];
            int j = ei[E + e];
            float rx = pos[3 * j + 0] - s_pi[0];
            float ry = pos[3 * j + 1] - s_pi[1];
            float rz = pos[3 * j + 2] - s_pi[2];
            float sx = (float)shifts[3 * e + 0];
            float sy = (float)shifts[3 * e + 1];
            float sz = (float)shifts[3 * e + 2];
            rx += sx * s_cell[0] + sy * s_cell[3] + sz * s_cell[6];
            ry += sx * s_cell[1] + sy * s_cell[4] + sz * s_cell[7];
            rz += sx * s_cell[2] + sy * s_cell[5] + sz * s_cell[8];

            float r2 = rx * rx + ry * ry + rz * rz + 1e-12f;
            float rinv = rsqrtf(r2);
            float r = r2 * rinv;
            float x = rx * rinv, y = ry * rinv, z = rz * rinv;

            float fcut = (r < 5.0f) ? 0.5f * (cospif(r * 0.2f) + 1.0f) : 0.0f;

            int sp = species[j];
            {   // radial: this thread owns n = sub
                float d = r - s_mu[sub];
                float Rn = __expf(-d * d * inv2s2) * fcut;
                wsh[eidx][0 * 8 + sub] = s_embed[4 * sp + 0] * Rn;
                wsh[eidx][1 * 8 + sub] = s_embed[4 * sp + 1] * Rn;
                wsh[eidx][2 * 8 + sub] = s_embed[4 * sp + 2] * Rn;
                wsh[eidx][3 * 8 + sub] = s_embed[4 * sp + 3] * Rn;
            }
            // spherical harmonics: this thread owns m = 2*sub, 2*sub+1
            float x2 = x * x, y2 = y * y, z2 = z * z;
            float ya, yb;
            switch (sub) {
                case 0: ya = 0.28209479177387814f;
                        yb = 0.4886025119029199f * y; break;
                case 1: ya = 0.4886025119029199f * z;
                        yb = 0.4886025119029199f * x; break;
                case 2: ya = 1.0925484305920792f * x * y;
                        yb = 1.0925484305920792f * y * z; break;
                case 3: ya = 0.31539156525252005f * (3.0f * z2 - 1.0f);
                        yb = 1.0925484305920792f * x * z; break;
                case 4: ya = 0.5462742152960396f * (x2 - y2);
                        yb = 0.5900435899266435f * y * (3.0f * x2 - y2); break;
                case 5: ya = 2.890611442640554f * x * y * z;
                        yb = 0.4570457994644658f * y * (5.0f * z2 - 1.0f); break;
                case 6: ya = 0.3731763325901154f * z * (5.0f * z2 - 3.0f);
                        yb = 0.4570457994644658f * x * (5.0f * z2 - 1.0f); break;
                default: ya = 1.445305721320277f * z * (x2 - y2);
                         yb = 0.5900435899266435f * x * (x2 - 3.0f * y2); break;
            }
            float2* yrow = (float2*)&Ysh[eidx][2 * sub];
            *yrow = make_float2(ya, yb);
        }
        __syncthreads();
        const float4* Y4 = (const float4*)Ysh;   // [edge][4] float4s
        if (ne == CH) {
#pragma unroll
            for (int e2i = 0; e2i < CH; e2i++) {
                float wv = wsh[e2i][q];
                float4 yv = Y4[e2i * 4 + w];     // broadcast LDS.128
                cacc0 = fmaf(yv.x, wv, cacc0);
                cacc1 = fmaf(yv.y, wv, cacc1);
                cacc2 = fmaf(yv.z, wv, cacc2);
                cacc3 = fmaf(yv.w, wv, cacc3);
            }
        } else {
            for (int e2i = 0; e2i < ne; e2i++) {
                float wv = wsh[e2i][q];
                float4 yv = Y4[e2i * 4 + w];
                cacc0 = fmaf(yv.x, wv, cacc0);
                cacc1 = fmaf(yv.y, wv, cacc1);
                cacc2 = fmaf(yv.z, wv, cacc2);
                cacc3 = fmaf(yv.w, wv, cacc3);
            }
        }
        __syncthreads();
    }

    csh[4 * w + 0][q] = cacc0;
    csh[4 * w + 1][q] = cacc1;
    csh[4 * w + 2][q] = cacc2;
    csh[4 * w + 3][q] = cacc3;
    __syncthreads();

    // epilogue: thread owns float4 column rb = t&7 and ADJACENT q-rows
    // {2qp, 2qp+1}, qp = t>>3. Per (l,k): one LDS.64 yields both a-scalars,
    // one broadcast LDS.128 yields the v-vector. Stores coalesced STG.128.
    {
        int rb = t & 7;
        int qp = t >> 3;           // 0..15 -> rows 2qp, 2qp+1
        const float4* csh4 = (const float4*)csh;   // [m][8]
        float4* out4 = (float4*)(out + (size_t)node * 4096);
        const float cgv[4] = {1.0f, 0.5773502691896258f,
                              0.4472135954999579f, 0.3779644730092272f};
        int m0 = 0;
#pragma unroll
        for (int l = 0; l < 4; l++) {
            int cnt = 2 * l + 1;
            float4 acc0 = make_float4(0.f, 0.f, 0.f, 0.f);
            float4 acc1 = make_float4(0.f, 0.f, 0.f, 0.f);
#pragma unroll 7
            for (int k = 0; k < 7; k++) {
                if (k < cnt) {
                    float4 v = csh4[(m0 + k) * 8 + rb];
                    float2 ap = *(const float2*)&csh[m0 + k][2 * qp];
                    acc0.x = fmaf(ap.x, v.x, acc0.x);
                    acc0.y = fmaf(ap.x, v.y, acc0.y);
                    acc0.z = fmaf(ap.x, v.z, acc0.z);
                    acc0.w = fmaf(ap.x, v.w, acc0.w);
                    acc1.x = fmaf(ap.y, v.x, acc1.x);
                    acc1.y = fmaf(ap.y, v.y, acc1.y);
                    acc1.z = fmaf(ap.y, v.z, acc1.z);
                    acc1.w = fmaf(ap.y, v.w, acc1.w);
                }
            }
            float cg = cgv[l];
            acc0.x *= cg; acc0.y *= cg; acc0.z *= cg; acc0.w *= cg;
            acc1.x *= cg; acc1.y *= cg; acc1.z *= cg; acc1.w *= cg;
            __stcs(&out4[l * 256 + (2 * qp) * 8 + rb], acc0);
            __stcs(&out4[l * 256 + (2 * qp + 1) * 8 + rb], acc1);
            m0 += cnt;
        }
    }

    // reset cursor for the next graph replay
    if (t == 0) d_count[node] = 0;
}

extern "C" void kernel_launch(void* const* d_in, const int* in_sizes, int n_in,
                              void* d_out, int out_size) {
    const float* pos     = (const float*)d_in[0];
    const float* cells   = (const float*)d_in[1];
    const int*   species = (const int*)  d_in[2];
    const int*   ei      = (const int*)  d_in[3];
    const int*   shifts  = (const int*)  d_in[4];
    const float* embed   = (const float*)d_in[5];
    const float* mu      = (const float*)d_in[6];
    const float* sigma   = (const float*)d_in[7];
    int N = in_sizes[0] / 3;
    int E = in_sizes[3] / 2;
    int E4 = E / 4;
    float* out = (float*)d_out;

    scatter_kernel<<<(E4 + 127) / 128, 128>>>((const int4*)ei, E4);
    ps_kernel<<<N, 128>>>(pos, cells, species, ei, shifts, embed, mu, sigma, out, N, E);
}

// round 9
// speedup vs baseline: 1.8545x; 1.0757x over previous
#include <cuda_runtime.h>

#define N_CAP 20480
#define E_CAP 327680
#define DEG_CAP 64      // fixed-stride edge-table width; deg ~ Poisson(16)
#define CH 16           // edges per accumulation chunk (8 subtask threads/edge)

// ---------------- device scratch ----------------
// d_count is zero at module load; ps_kernel re-zeros its node at the end of
// every call, so each graph replay starts from a clean cursor.
__device__ int d_count[N_CAP];
__device__ int d_elist[N_CAP * DEG_CAP];
__device__ float4 d_erec[E_CAP];   // per-edge: (pos[j]+shift@cell, j|sp<<24)

// ---------------- phase 1: scatter + edge-record packing -------------------
// One thread per edge: bins the edge under node i AND materializes the
// 16-byte record that ps_kernel's gather will read with a single LDG.128.
__global__ void scatter_kernel(const int* __restrict__ ei,
                               const float* __restrict__ pos,
                               const int* __restrict__ species,
                               const int* __restrict__ shifts,
                               const float* __restrict__ cells, int E) {
    int e = blockIdx.x * blockDim.x + threadIdx.x;
    if (e >= E) return;
    int i = ei[e];
    int j = ei[E + e];
    float px = pos[3 * j + 0];
    float py = pos[3 * j + 1];
    float pz = pos[3 * j + 2];
    float sx = (float)shifts[3 * e + 0];
    float sy = (float)shifts[3 * e + 1];
    float sz = (float)shifts[3 * e + 2];
    px += sx * cells[0] + sy * cells[3] + sz * cells[6];
    py += sx * cells[1] + sy * cells[4] + sz * cells[7];
    pz += sx * cells[2] + sy * cells[5] + sz * cells[8];
    int sp = species[j];
    d_erec[e] = make_float4(px, py, pz, __int_as_float(j | (sp << 24)));
    int p = atomicAdd(&d_count[i], 1);
    if (p < DEG_CAP) d_elist[i * DEG_CAP + p] = e;
}

// ---------------- phase 2: per-node features + power spectrum --------------
__global__ __launch_bounds__(128, 12) void ps_kernel(
    const float* __restrict__ pos, const float* __restrict__ embed,
    const float* __restrict__ mu, const float* __restrict__ sigma,
    float* __restrict__ out, int N)
{
    __shared__ __align__(16) float Ysh[CH][16];  // [edge][m]: 64B rows
    __shared__ float wsh[CH][40];                // [edge][q], pad 40
    __shared__ __align__(16) float csh[16][32];  // [m][q]
    __shared__ int   elist[DEG_CAP];
    __shared__ int   esort[DEG_CAP];
    __shared__ float s_embed[16];
    __shared__ float s_mu[8];
    __shared__ float s_pi[3];

    int node = blockIdx.x;
    int t = threadIdx.x;

    if (t < 16) s_embed[t] = embed[t];
    if (t < 8)  s_mu[t] = mu[t];
    if (t < 3)  s_pi[t] = pos[3 * node + t];

    int deg = d_count[node];
    if (deg > DEG_CAP) deg = DEG_CAP;

    for (int k = t; k < deg; k += 128) elist[k] = d_elist[node * DEG_CAP + k];
    __syncthreads();
    // deterministic accumulation order: rank-sort unique edge ids
    for (int k = t; k < deg; k += 128) {
        int e = elist[k], rank = 0;
        for (int x = 0; x < deg; x++) rank += (elist[x] < e);
        esort[rank] = e;
    }
    __syncthreads();

    float sg = sigma[0];
    float inv2s2 = 1.0f / (2.0f * sg * sg);

    int w = t >> 5;   // warp id: owns m = 4w..4w+3
    int q = t & 31;   // lane
    float cacc0 = 0.0f, cacc1 = 0.0f, cacc2 = 0.0f, cacc3 = 0.0f;

    int eidx = t >> 3;   // 0..15: edge within chunk
    int sub  = t & 7;    // 0..7: subtask

    for (int base = 0; base < deg; base += CH) {
        int ne = deg - base; if (ne > CH) ne = CH;
        if (eidx < ne) {
            int e = esort[base + eidx];
            float4 rec = __ldg(&d_erec[e]);   // one broadcast LDG.128 per edge
            float rx = rec.x - s_pi[0];
            float ry = rec.y - s_pi[1];
            float rz = rec.z - s_pi[2];
            int sp = __float_as_int(rec.w) >> 24;

            float r2 = rx * rx + ry * ry + rz * rz + 1e-12f;
            float rinv = rsqrtf(r2);
            float r = r2 * rinv;
            float x = rx * rinv, y = ry * rinv, z = rz * rinv;

            float fcut = (r < 5.0f) ? 0.5f * (cospif(r * 0.2f) + 1.0f) : 0.0f;

            {   // radial: this thread owns n = sub
                float d = r - s_mu[sub];
                float Rn = __expf(-d * d * inv2s2) * fcut;
                wsh[eidx][0 * 8 + sub] = s_embed[4 * sp + 0] * Rn;
                wsh[eidx][1 * 8 + sub] = s_embed[4 * sp + 1] * Rn;
                wsh[eidx][2 * 8 + sub] = s_embed[4 * sp + 2] * Rn;
                wsh[eidx][3 * 8 + sub] = s_embed[4 * sp + 3] * Rn;
            }
            // spherical harmonics: this thread owns m = 2*sub, 2*sub+1
            float x2 = x * x, y2 = y * y, z2 = z * z;
            float ya, yb;
            switch (sub) {
                case 0: ya = 0.28209479177387814f;
                        yb = 0.4886025119029199f * y; break;
                case 1: ya = 0.4886025119029199f * z;
                        yb = 0.4886025119029199f * x; break;
                case 2: ya = 1.0925484305920792f * x * y;
                        yb = 1.0925484305920792f * y * z; break;
                case 3: ya = 0.31539156525252005f * (3.0f * z2 - 1.0f);
                        yb = 1.0925484305920792f * x * z; break;
                case 4: ya = 0.5462742152960396f * (x2 - y2);
                        yb = 0.5900435899266435f * y * (3.0f * x2 - y2); break;
                case 5: ya = 2.890611442640554f * x * y * z;
                        yb = 0.4570457994644658f * y * (5.0f * z2 - 1.0f); break;
                case 6: ya = 0.3731763325901154f * z * (5.0f * z2 - 3.0f);
                        yb = 0.4570457994644658f * x * (5.0f * z2 - 1.0f); break;
                default: ya = 1.445305721320277f * z * (x2 - y2);
                         yb = 0.5900435899266435f * x * (x2 - 3.0f * y2); break;
            }
            float2* yrow = (float2*)&Ysh[eidx][2 * sub];
            *yrow = make_float2(ya, yb);
        }
        __syncthreads();
        const float4* Y4 = (const float4*)Ysh;   // [edge][4] float4s
        if (ne == CH) {
#pragma unroll
            for (int e2i = 0; e2i < CH; e2i++) {
                float wv = wsh[e2i][q];
                float4 yv = Y4[e2i * 4 + w];     // broadcast LDS.128
                cacc0 = fmaf(yv.x, wv, cacc0);
                cacc1 = fmaf(yv.y, wv, cacc1);
                cacc2 = fmaf(yv.z, wv, cacc2);
                cacc3 = fmaf(yv.w, wv, cacc3);
            }
        } else {
            for (int e2i = 0; e2i < ne; e2i++) {
                float wv = wsh[e2i][q];
                float4 yv = Y4[e2i * 4 + w];
                cacc0 = fmaf(yv.x, wv, cacc0);
                cacc1 = fmaf(yv.y, wv, cacc1);
                cacc2 = fmaf(yv.z, wv, cacc2);
                cacc3 = fmaf(yv.w, wv, cacc3);
            }
        }
        __syncthreads();
    }

    csh[4 * w + 0][q] = cacc0;
    csh[4 * w + 1][q] = cacc1;
    csh[4 * w + 2][q] = cacc2;
    csh[4 * w + 3][q] = cacc3;
    __syncthreads();

    // epilogue: thread owns float4 column rb = t&7 and adjacent q-rows
    // {2qp, 2qp+1}; per (l,m): one LDS.64 (both a-scalars) + one broadcast
    // LDS.128 (v-vector). Stores coalesced STG.128 streaming.
    {
        int rb = t & 7;
        int qp = t >> 3;           // 0..15 -> rows 2qp, 2qp+1
        const float4* csh4 = (const float4*)csh;   // [m][8]
        float4* out4 = (float4*)(out + (size_t)node * 4096);
        const float cgv[4] = {1.0f, 0.5773502691896258f,
                              0.4472135954999579f, 0.3779644730092272f};
        int m0 = 0;
#pragma unroll
        for (int l = 0; l < 4; l++) {
            int cnt = 2 * l + 1;
            float4 acc0 = make_float4(0.f, 0.f, 0.f, 0.f);
            float4 acc1 = make_float4(0.f, 0.f, 0.f, 0.f);
#pragma unroll 7
            for (int k = 0; k < 7; k++) {
                if (k < cnt) {
                    float4 v = csh4[(m0 + k) * 8 + rb];
                    float2 ap = *(const float2*)&csh[m0 + k][2 * qp];
                    acc0.x = fmaf(ap.x, v.x, acc0.x);
                    acc0.y = fmaf(ap.x, v.y, acc0.y);
                    acc0.z = fmaf(ap.x, v.z, acc0.z);
                    acc0.w = fmaf(ap.x, v.w, acc0.w);
                    acc1.x = fmaf(ap.y, v.x, acc1.x);
                    acc1.y = fmaf(ap.y, v.y, acc1.y);
                    acc1.z = fmaf(ap.y, v.z, acc1.z);
                    acc1.w = fmaf(ap.y, v.w, acc1.w);
                }
            }
            float cg = cgv[l];
            acc0.x *= cg; acc0.y *= cg; acc0.z *= cg; acc0.w *= cg;
            acc1.x *= cg; acc1.y *= cg; acc1.z *= cg; acc1.w *= cg;
            __stcs(&out4[l * 256 + (2 * qp) * 8 + rb], acc0);
            __stcs(&out4[l * 256 + (2 * qp + 1) * 8 + rb], acc1);
            m0 += cnt;
        }
    }

    // reset cursor for the next graph replay
    if (t == 0) d_count[node] = 0;
}

extern "C" void kernel_launch(void* const* d_in, const int* in_sizes, int n_in,
                              void* d_out, int out_size) {
    const float* pos     = (const float*)d_in[0];
    const float* cells   = (const float*)d_in[1];
    const int*   species = (const int*)  d_in[2];
    const int*   ei      = (const int*)  d_in[3];
    const int*   shifts  = (const int*)  d_in[4];
    const float* embed   = (const float*)d_in[5];
    const float* mu      = (const float*)d_in[6];
    const float* sigma   = (const float*)d_in[7];
    int N = in_sizes[0] / 3;
    int E = in_sizes[3] / 2;
    float* out = (float*)d_out;

    scatter_kernel<<<(E + 255) / 256, 256>>>(ei, pos, species, shifts, cells, E);
    ps_kernel<<<N, 128>>>(pos, embed, mu, sigma, out, N);
}